// round 4
// baseline (speedup 1.0000x reference)
#include <cuda_runtime.h>
#include <math.h>
#include <stdint.h>

#define AA 3072   // A = BS * IA
#define DD 2048   // D = BS * (IA-1)
#define NB 1024   // BS

// scratch ping-pong buffers (no device allocation allowed)
__device__ float g_buf0[AA];
__device__ float g_buf1[AA];

__device__ __forceinline__ uint32_t smem_u32(const void* p) {
    uint32_t a;
    asm("{ .reg .u64 t; cvta.to.shared.u64 t, %1; cvt.u32.u64 %0, t; }"
        : "=r"(a) : "l"(p));
    return a;
}

__device__ __forceinline__ void mbar_wait(uint32_t mbar, uint32_t phase) {
    asm volatile(
        "{\n\t"
        ".reg .pred P;\n\t"
        "W%=:\n\t"
        "mbarrier.try_wait.parity.acquire.cta.shared::cta.b64 P, [%0], %1, 0x989680;\n\t"
        "@!P bra W%=;\n\t"
        "}"
        :: "r"(mbar), "r"(phase) : "memory");
}

// ---------------------------------------------------------------------------
// GEMV via TMA bulk copy: 2 rows per block.
// One cp.async.bulk pulls the 2-row W tile into smem (huge DRAM MLP,
// zero register pressure); 256 threads then dot it against x from L1.
// ACT: 0 = none, 1 = tanh, 2 = tanhshrink (h - tanh(h))
// ---------------------------------------------------------------------------
template<int ACT, int COLS>
__global__ void __launch_bounds__(256) gemv_tma(const float* __restrict__ W,
                                                const float* __restrict__ x,
                                                const float* __restrict__ b,
                                                float* __restrict__ y)
{
    constexpr int N4   = COLS / 4;          // 768 or 512 float4 per row
    constexpr int IT   = N4 / 256;          // 3 or 2 per thread per row
    constexpr uint32_t TILE_BYTES = 2u * COLS * 4u;

    extern __shared__ float sW[];           // 2 * COLS floats
    __shared__ __align__(8) unsigned long long mbar;

    const uint32_t mb = smem_u32(&mbar);
    const int row0 = blockIdx.x * 2;

    if (threadIdx.x == 0)
        asm volatile("mbarrier.init.shared.b64 [%0], 1;" :: "r"(mb));
    __syncthreads();

    if (threadIdx.x == 0) {
        asm volatile("mbarrier.arrive.expect_tx.shared.b64 _, [%0], %1;"
                     :: "r"(mb), "r"(TILE_BYTES) : "memory");
        asm volatile(
            "cp.async.bulk.shared::cta.global.mbarrier::complete_tx::bytes "
            "[%0], [%1], %2, [%3];"
            :: "r"(smem_u32(sW)),
               "l"(W + (size_t)row0 * COLS),
               "r"(TILE_BYTES), "r"(mb)
            : "memory");
    }

    // x loads overlap with the bulk copy (L1/L2-resident after first block)
    const float4* __restrict__ x4 = reinterpret_cast<const float4*>(x);
    float4 v[IT];
    #pragma unroll
    for (int k = 0; k < IT; ++k) v[k] = x4[threadIdx.x + k * 256];

    mbar_wait(mb, 0);

    const float4* sW4 = reinterpret_cast<const float4*>(sW);
    float acc[2];
    #pragma unroll
    for (int r = 0; r < 2; ++r) {
        float a = 0.f;
        #pragma unroll
        for (int k = 0; k < IT; ++k) {
            float4 w = sW4[r * N4 + threadIdx.x + k * 256];
            a = fmaf(w.x, v[k].x, a);
            a = fmaf(w.y, v[k].y, a);
            a = fmaf(w.z, v[k].z, a);
            a = fmaf(w.w, v[k].w, a);
        }
        acc[r] = a;
    }

    // warp reduce both rows
    #pragma unroll
    for (int r = 0; r < 2; ++r)
        #pragma unroll
        for (int off = 16; off; off >>= 1)
            acc[r] += __shfl_xor_sync(0xFFFFFFFFu, acc[r], off);

    __shared__ float sp[16];
    const int lane = threadIdx.x & 31;
    const int warp = threadIdx.x >> 5;
    if (lane == 0) { sp[warp * 2] = acc[0]; sp[warp * 2 + 1] = acc[1]; }
    __syncthreads();

    if (threadIdx.x < 16) {
        // thread t holds partial for (warp = t>>1, row = t&1)
        float s = sp[threadIdx.x];
        s += __shfl_xor_sync(0xFFFFu, s, 2);
        s += __shfl_xor_sync(0xFFFFu, s, 4);
        s += __shfl_xor_sync(0xFFFFu, s, 8);
        if (threadIdx.x < 2) {
            float h = s + b[row0 + threadIdx.x];
            if (ACT == 1)      h = tanhf(h);
            else if (ACT == 2) h = h - tanhf(h);
            y[row0 + threadIdx.x] = h;
        }
    }
}

// ---------------------------------------------------------------------------
// pdist: out[i*1024 + j] = || a[i,:] - a[j,:] ||_2   (a: [1024, DIMS])
// ---------------------------------------------------------------------------
template<int DIMS>
__global__ void __launch_bounds__(256) pdist_kernel(const float* __restrict__ a,
                                                    float* __restrict__ out)
{
    __shared__ float s[NB * DIMS];
    for (int t = threadIdx.x; t < NB * DIMS; t += 256) s[t] = a[t];
    __syncthreads();

    const int idx = blockIdx.x * 256 + threadIdx.x;   // 0 .. 1024*1024-1
    const int i = idx >> 10;
    const int j = idx & (NB - 1);

    float d2 = 0.f;
    #pragma unroll
    for (int k = 0; k < DIMS; ++k) {
        float d = s[i * DIMS + k] - s[j * DIMS + k];
        d2 = fmaf(d, d, d2);
    }
    out[idx] = sqrtf(d2);
}

// ---------------------------------------------------------------------------
// kernel_launch: encoder (4 GEMV) -> pdists -> decoder (4 GEMV)
// output layout: [output(3072) | in_diff(1024^2) | lat_diff(1024^2) | lat_repr(2048)]
// ---------------------------------------------------------------------------
extern "C" void kernel_launch(void* const* d_in, const int* in_sizes, int n_in,
                              void* d_out, int out_size)
{
    (void)in_sizes; (void)n_in; (void)out_size;

    const float* x   = (const float*)d_in[0];
    const float* ew1 = (const float*)d_in[1];
    const float* eb1 = (const float*)d_in[2];
    const float* ew2 = (const float*)d_in[3];
    const float* eb2 = (const float*)d_in[4];
    const float* ew3 = (const float*)d_in[5];
    const float* eb3 = (const float*)d_in[6];
    const float* ew4 = (const float*)d_in[7];
    const float* eb4 = (const float*)d_in[8];
    const float* dw1 = (const float*)d_in[9];
    const float* db1 = (const float*)d_in[10];
    const float* dw2 = (const float*)d_in[11];
    const float* db2 = (const float*)d_in[12];
    const float* dw3 = (const float*)d_in[13];
    const float* db3 = (const float*)d_in[14];
    const float* dw4 = (const float*)d_in[15];
    const float* db4 = (const float*)d_in[16];

    float* out      = (float*)d_out;
    float* out_main = out;                          // 3072
    float* out_ind  = out + AA;                     // 1024*1024
    float* out_lat  = out + AA + NB * NB;           // 1024*1024
    float* y        = out + AA + 2 * NB * NB;       // 2048 (lat_repr / encoder out)

    float *buf0, *buf1;
    cudaGetSymbolAddress((void**)&buf0, g_buf0);
    cudaGetSymbolAddress((void**)&buf1, g_buf1);

    constexpr int SM_A = 2 * AA * 4;   // 24576 bytes (COLS=3072 tile)
    constexpr int SM_D = 2 * DD * 4;   // 16384 bytes (COLS=2048 tile)

    // in_data pdist depends only on x — issue first
    pdist_kernel<3><<<(NB * NB) / 256, 256>>>(x, out_ind);

    // encoder
    gemv_tma<1, AA><<<AA / 2, 256, SM_A>>>(ew1, x,    eb1, buf0);
    gemv_tma<1, AA><<<AA / 2, 256, SM_A>>>(ew2, buf0, eb2, buf1);
    gemv_tma<0, AA><<<AA / 2, 256, SM_A>>>(ew3, buf1, eb3, buf0);
    gemv_tma<2, AA><<<DD / 2, 256, SM_A>>>(ew4, buf0, eb4, y);   // tanhshrink

    // latent pdist
    pdist_kernel<2><<<(NB * NB) / 256, 256>>>(y, out_lat);

    // decoder (final layer fuses the output tanh)
    gemv_tma<1, DD><<<AA / 2, 256, SM_D>>>(dw1, y,    db1, buf0);
    gemv_tma<1, AA><<<AA / 2, 256, SM_A>>>(dw2, buf0, db2, buf1);
    gemv_tma<0, AA><<<AA / 2, 256, SM_A>>>(dw3, buf1, db3, buf0);
    gemv_tma<1, AA><<<AA / 2, 256, SM_A>>>(dw4, buf0, db4, out_main);
}

// round 5
// speedup vs baseline: 1.1084x; 1.1084x over previous
#include <cuda_runtime.h>
#include <math.h>

#define AA 3072   // A = BS * IA
#define DD 2048   // D = BS * (IA-1)
#define NB 1024   // BS

// scratch ping-pong buffers (no device allocation allowed)
__device__ float g_buf0[AA];
__device__ float g_buf1[AA];

// ---------------------------------------------------------------------------
// GEMV, warp-per-row with explicit deep load pipeline.
// 8 rows per block (256 thr). Per lane: PER_LANE float4 of W, consumed in
// batches of 8 independent __ldcs loads, double-buffered in registers.
// __launch_bounds__(256,2) grants a 128-reg budget so ptxas keeps the
// batches parallel (64 regs of W buffers alone).
// ACT: 0 = none, 1 = tanh, 2 = tanhshrink (h - tanh(h))
// ---------------------------------------------------------------------------
template<int ACT, int COLS>
__global__ void __launch_bounds__(256, 2)
gemv_ws(const float* __restrict__ W, const float* __restrict__ x,
        const float* __restrict__ b, float* __restrict__ y)
{
    constexpr int F4       = COLS / 4;     // 768 or 512 float4 per row
    constexpr int PER_LANE = F4 / 32;      // 24 or 16
    constexpr int NBATCH   = PER_LANE / 8; // 3 or 2

    __shared__ float sx[COLS];

    const int lane = threadIdx.x & 31;
    const int warp = threadIdx.x >> 5;
    const int row  = blockIdx.x * 8 + warp;

    const float4* __restrict__ W4 =
        reinterpret_cast<const float4*>(W + (size_t)row * COLS);

    // stage x into shared (3 or 2 float4 per thread)
    const float4* __restrict__ xg4 = reinterpret_cast<const float4*>(x);
    float4* sx4 = reinterpret_cast<float4*>(sx);
    #pragma unroll
    for (int k = 0; k < F4 / 256; ++k)
        sx4[threadIdx.x + 256 * k] = xg4[threadIdx.x + 256 * k];

    // prologue: batch 0 of W issued BEFORE the barrier (independent of smem)
    float4 buf[2][8];
    #pragma unroll
    for (int t = 0; t < 8; ++t)
        buf[0][t] = __ldcs(&W4[lane + 32 * t]);

    __syncthreads();

    float a0 = 0.f, a1 = 0.f, a2 = 0.f, a3 = 0.f;
    #pragma unroll
    for (int bt = 0; bt < NBATCH; ++bt) {
        const int cur = bt & 1;
        if (bt + 1 < NBATCH) {
            #pragma unroll
            for (int t = 0; t < 8; ++t)
                buf[cur ^ 1][t] = __ldcs(&W4[lane + 32 * (8 * (bt + 1) + t)]);
        }
        #pragma unroll
        for (int t = 0; t < 8; ++t) {
            float4 v = sx4[lane + 32 * (8 * bt + t)];
            a0 = fmaf(buf[cur][t].x, v.x, a0);
            a1 = fmaf(buf[cur][t].y, v.y, a1);
            a2 = fmaf(buf[cur][t].z, v.z, a2);
            a3 = fmaf(buf[cur][t].w, v.w, a3);
        }
    }
    float acc = (a0 + a1) + (a2 + a3);

    #pragma unroll
    for (int off = 16; off; off >>= 1)
        acc += __shfl_xor_sync(0xFFFFFFFFu, acc, off);

    if (lane == 0) {
        float h = acc + b[row];
        if (ACT == 1)      h = tanhf(h);
        else if (ACT == 2) h = h - tanhf(h);
        y[row] = h;
    }
}

// ---------------------------------------------------------------------------
// pdist: out[i*1024 + j] = || a[i,:] - a[j,:] ||_2   (a: [1024, DIMS])
// ---------------------------------------------------------------------------
template<int DIMS>
__global__ void __launch_bounds__(256) pdist_kernel(const float* __restrict__ a,
                                                    float* __restrict__ out)
{
    __shared__ float s[NB * DIMS];
    for (int t = threadIdx.x; t < NB * DIMS; t += 256) s[t] = a[t];
    __syncthreads();

    const int idx = blockIdx.x * 256 + threadIdx.x;   // 0 .. 1024*1024-1
    const int i = idx >> 10;
    const int j = idx & (NB - 1);

    float d2 = 0.f;
    #pragma unroll
    for (int k = 0; k < DIMS; ++k) {
        float d = s[i * DIMS + k] - s[j * DIMS + k];
        d2 = fmaf(d, d, d2);
    }
    out[idx] = sqrtf(d2);
}

// ---------------------------------------------------------------------------
// kernel_launch: encoder (4 GEMV) -> pdists -> decoder (4 GEMV)
// output layout: [output(3072) | in_diff(1024^2) | lat_diff(1024^2) | lat_repr(2048)]
// ---------------------------------------------------------------------------
extern "C" void kernel_launch(void* const* d_in, const int* in_sizes, int n_in,
                              void* d_out, int out_size)
{
    (void)in_sizes; (void)n_in; (void)out_size;

    const float* x   = (const float*)d_in[0];
    const float* ew1 = (const float*)d_in[1];
    const float* eb1 = (const float*)d_in[2];
    const float* ew2 = (const float*)d_in[3];
    const float* eb2 = (const float*)d_in[4];
    const float* ew3 = (const float*)d_in[5];
    const float* eb3 = (const float*)d_in[6];
    const float* ew4 = (const float*)d_in[7];
    const float* eb4 = (const float*)d_in[8];
    const float* dw1 = (const float*)d_in[9];
    const float* db1 = (const float*)d_in[10];
    const float* dw2 = (const float*)d_in[11];
    const float* db2 = (const float*)d_in[12];
    const float* dw3 = (const float*)d_in[13];
    const float* db3 = (const float*)d_in[14];
    const float* dw4 = (const float*)d_in[15];
    const float* db4 = (const float*)d_in[16];

    float* out      = (float*)d_out;
    float* out_main = out;                          // 3072
    float* out_ind  = out + AA;                     // 1024*1024
    float* out_lat  = out + AA + NB * NB;           // 1024*1024
    float* y        = out + AA + 2 * NB * NB;       // 2048 (lat_repr / encoder out)

    float *buf0, *buf1;
    cudaGetSymbolAddress((void**)&buf0, g_buf0);
    cudaGetSymbolAddress((void**)&buf1, g_buf1);

    // in_data pdist depends only on x — issue first
    pdist_kernel<3><<<(NB * NB) / 256, 256>>>(x, out_ind);

    // encoder
    gemv_ws<1, AA><<<AA / 8, 256>>>(ew1, x,    eb1, buf0);
    gemv_ws<1, AA><<<AA / 8, 256>>>(ew2, buf0, eb2, buf1);
    gemv_ws<0, AA><<<AA / 8, 256>>>(ew3, buf1, eb3, buf0);
    gemv_ws<2, AA><<<DD / 8, 256>>>(ew4, buf0, eb4, y);    // tanhshrink -> lat_repr

    // latent pdist
    pdist_kernel<2><<<(NB * NB) / 256, 256>>>(y, out_lat);

    // decoder (final layer fuses the output tanh)
    gemv_ws<1, DD><<<AA / 8, 256>>>(dw1, y,    db1, buf0);
    gemv_ws<1, AA><<<AA / 8, 256>>>(dw2, buf0, db2, buf1);
    gemv_ws<0, AA><<<AA / 8, 256>>>(dw3, buf1, db3, buf0);
    gemv_ws<1, AA><<<AA / 8, 256>>>(dw4, buf0, db4, out_main);
}